// round 2
// baseline (speedup 1.0000x reference)
#include <cuda_runtime.h>

// ---------------------------------------------------------------------------
// GraphConstruction: A[i,j] = all_k( ||patch_i[:,k]-patch_j[:,k]||_2 <= 7 )
// N = 4096 patches, 16x16. Augmented-18-row Gram formulation:
//   score_k(i,j) = sum_{r<16} P[i,r,k]*P[j,r,k] + 1*(12.25-0.5*sq_jk)
//                + (12.25-0.5*sq_ik)*1   >= 0   <=>  d2 <= 49
// A[i,j] = (min_k score_k >= 0).  Math order identical to R0 (rel_err-stable).
// ---------------------------------------------------------------------------

#define NP 4096
#define RAUG 18

// [k][r][n] layout, k<16, r<18, n<4096.  4.5 MB scratch.
static __device__ float g_P[16 * RAUG * NP];

// ---------------- f32x2 packed-FMA helpers (sm_103a) -----------------------
__device__ __forceinline__ unsigned long long bcast2(float x) {
    unsigned long long r;
    asm("mov.b64 %0, {%1, %1};" : "=l"(r) : "f"(x));
    return r;
}
__device__ __forceinline__ void ffma2(unsigned long long& d,
                                      unsigned long long a,
                                      unsigned long long b) {
    asm("fma.rn.f32x2 %0, %1, %2, %3;" : "=l"(d) : "l"(a), "l"(b), "l"(d));
}
__device__ __forceinline__ float2 unpk2(unsigned long long v) {
    float2 f;
    asm("mov.b64 {%0, %1}, %2;" : "=f"(f.x), "=f"(f.y) : "l"(v));
    return f;
}
__device__ __forceinline__ void cp_async16(void* smem, const void* gmem) {
    unsigned s = (unsigned)__cvta_generic_to_shared(smem);
    asm volatile("cp.async.cg.shared.global [%0], [%1], 16;" :: "r"(s), "l"(gmem));
}
#define CP_COMMIT() asm volatile("cp.async.commit_group;")

// ---------------- prep 1: gather x into g_P rows 0..15 ---------------------
// 4 consecutive n per thread -> float4 coalesced store, MLP=4 scattered loads.
__global__ void prep1_kernel(const float* __restrict__ x) {
    int idx = blockIdx.x * blockDim.x + threadIdx.x;   // [0, 16*16*1024)
    int n4 = idx & 1023;
    int rk = idx >> 10;          // k*16 + r
    int k = rk >> 4;
    int r = rk & 15;
    float v[4];
#pragma unroll
    for (int c = 0; c < 4; c++) {
        int n = n4 * 4 + c;
        int h = ((4 * (n & 15) + (r >> 2)) << 4) + (n >> 8);
        int w = ((16 * (r & 3) + k) << 4) + ((n >> 4) & 15);
        v[c] = x[h * 1024 + w];
    }
    *(float4*)&g_P[(k * RAUG + r) * NP + n4 * 4] =
        make_float4(v[0], v[1], v[2], v[3]);
}

// ---------------- prep 2: augmentation rows 16,17 ---------------------------
// Per-n scalar fmaf chain r=0..15 (identical rounding to R0).
__global__ void prep2_kernel() {
    int idx = blockIdx.x * blockDim.x + threadIdx.x;   // [0, 16*1024)
    int n4 = idx & 1023;
    int k = idx >> 10;
    float s[4] = {0.0f, 0.0f, 0.0f, 0.0f};
#pragma unroll
    for (int r = 0; r < 16; r++) {
        float4 v = *(const float4*)&g_P[(k * RAUG + r) * NP + n4 * 4];
        s[0] = fmaf(v.x, v.x, s[0]);
        s[1] = fmaf(v.y, v.y, s[1]);
        s[2] = fmaf(v.z, v.z, s[2]);
        s[3] = fmaf(v.w, v.w, s[3]);
    }
    *(float4*)&g_P[(k * RAUG + 16) * NP + n4 * 4] =
        make_float4(1.0f, 1.0f, 1.0f, 1.0f);
    *(float4*)&g_P[(k * RAUG + 17) * NP + n4 * 4] =
        make_float4(12.25f - 0.5f * s[0], 12.25f - 0.5f * s[1],
                    12.25f - 0.5f * s[2], 12.25f - 0.5f * s[3]);
}

// ---------------- main: tiled pair kernel -----------------------------------
// Tile: 64 i x 128 j.  256 threads, each owns 4x8 pairs (j packed as f32x2).
// 1D grid of exactly the 1056 triangle tiles (ib <= 2*jb+1).
__global__ void __launch_bounds__(256, 2) gram_kernel(float* __restrict__ A) {
    const int bid = blockIdx.x;
    // decode bid -> (jb, ib): cumulative count before jb is jb*(jb+1)
    int jb = (int)(0.5f * (sqrtf(4.0f * (float)bid + 1.0f) - 1.0f));
    while (jb * (jb + 1) > bid) jb--;
    while ((jb + 1) * (jb + 2) <= bid) jb++;
    const int ib = bid - jb * (jb + 1);        // 0 .. 2*jb+1 (<= 63)

    __shared__ __align__(16) float sA[2][RAUG][64];
    __shared__ __align__(16) float sB[2][RAUG][128];

    const int tid = threadIdx.x;
    const int tx = tid & 15;             // j group (8 j's, packed as 4 f32x2)
    const int ty = tid >> 4;             // i group 0..15 (4 i's)
    const int i0 = ib * 64;
    const int j0 = jb * 128;

    auto issue = [&](int buf, int k) {
        // sA: 18 rows x 64 floats = 288 float4
#pragma unroll
        for (int idx = tid; idx < 288; idx += 256) {
            int r = idx >> 4, c = idx & 15;
            cp_async16(&sA[buf][r][c * 4], &g_P[(k * RAUG + r) * NP + i0 + c * 4]);
        }
        // sB: 18 rows x 128 floats = 576 float4 (rows 16/17 swapped)
#pragma unroll
        for (int idx = tid; idx < 576; idx += 256) {
            int r = idx >> 5, c = idx & 31;
            int rs = (r < 16) ? r : (33 - r);
            cp_async16(&sB[buf][r][c * 4], &g_P[(k * RAUG + rs) * NP + j0 + c * 4]);
        }
    };

    float mn[4][8];
#pragma unroll
    for (int a = 0; a < 4; a++)
#pragma unroll
        for (int b = 0; b < 8; b++) mn[a][b] = 1.0e30f;

    issue(0, 0);
    CP_COMMIT();

#pragma unroll 1
    for (int k = 0; k < 16; k++) {
        const int buf = k & 1;
        if (k < 15) {
            issue(buf ^ 1, k + 1);
            CP_COMMIT();
            asm volatile("cp.async.wait_group 1;");
        } else {
            asm volatile("cp.async.wait_group 0;");
        }
        __syncthreads();   // buf fully staged, visible to all

        unsigned long long acc[4][4];
#pragma unroll
        for (int a = 0; a < 4; a++)
#pragma unroll
            for (int b = 0; b < 4; b++) acc[a][b] = 0ULL;

#pragma unroll
        for (int r = 0; r < RAUG; r++) {
            float4 a0 = *(const float4*)&sA[buf][r][ty * 4];
            ulonglong2 b0 = *(const ulonglong2*)&sB[buf][r][tx * 8];
            ulonglong2 b1 = *(const ulonglong2*)&sB[buf][r][tx * 8 + 4];
            unsigned long long bb[4] = {b0.x, b0.y, b1.x, b1.y};
            float av[4] = {a0.x, a0.y, a0.z, a0.w};
#pragma unroll
            for (int ii = 0; ii < 4; ii++) {
                unsigned long long aa = bcast2(av[ii]);
#pragma unroll
                for (int jj = 0; jj < 4; jj++) ffma2(acc[ii][jj], aa, bb[jj]);
            }
        }

        // fold this k's scores into running min
#pragma unroll
        for (int ii = 0; ii < 4; ii++)
#pragma unroll
            for (int jj = 0; jj < 4; jj++) {
                float2 v = unpk2(acc[ii][jj]);
                mn[ii][jj * 2]     = fminf(mn[ii][jj * 2], v.x);
                mn[ii][jj * 2 + 1] = fminf(mn[ii][jj * 2 + 1], v.y);
            }

        __syncthreads();   // compute(buf) done before next iter overwrites it
    }

    // threshold -> 0/1
#pragma unroll
    for (int ii = 0; ii < 4; ii++)
#pragma unroll
        for (int jj = 0; jj < 8; jj++)
            mn[ii][jj] = (mn[ii][jj] >= 0.0f) ? 1.0f : 0.0f;

    // direct tile write: A[i, j]
#pragma unroll
    for (int ii = 0; ii < 4; ii++) {
        size_t row = (size_t)(i0 + ty * 4 + ii) * 4096 + j0 + tx * 8;
        *(float4*)&A[row]     = make_float4(mn[ii][0], mn[ii][1], mn[ii][2], mn[ii][3]);
        *(float4*)&A[row + 4] = make_float4(mn[ii][4], mn[ii][5], mn[ii][6], mn[ii][7]);
    }
    // transposed write: A[j, i]  (i contiguous -> one float4 per j row)
#pragma unroll
    for (int jj = 0; jj < 8; jj++) {
        size_t row = (size_t)(j0 + tx * 8 + jj) * 4096 + i0 + ty * 4;
        *(float4*)&A[row] = make_float4(mn[0][jj], mn[1][jj], mn[2][jj], mn[3][jj]);
    }
}

// ---------------------------------------------------------------------------
extern "C" void kernel_launch(void* const* d_in, const int* in_sizes, int n_in,
                              void* d_out, int out_size) {
    const float* x = (const float*)d_in[0];
    float* A = (float*)d_out;

    prep1_kernel<<<1024, 256>>>(x);        // 16*16*1024 thread-groups of 4 n
    prep2_kernel<<<64, 256>>>();           // 16*1024 thread-groups of 4 n
    gram_kernel<<<1056, 256>>>(A);         // exact triangle of 64x128 tiles
}

// round 3
// speedup vs baseline: 1.7203x; 1.7203x over previous
#include <cuda_runtime.h>

// ---------------------------------------------------------------------------
// GraphConstruction: A[i,j] = all_k( ||patch_i[:,k]-patch_j[:,k]||_2 <= 7 )
// score_k(i,j) = sum_{r<16} P[i,r,k]*P[j,r,k] + 1*c_j + c_i*1,  c = 12.25-sq/2
// A[i,j] = no k has score_k < 0  (OR of sign bits == 0).
// FMA order identical to R0/R1 (rel_err bit-stable).
// ---------------------------------------------------------------------------

#define NP 4096
#define RAUG 18

static __device__ float g_P[16 * RAUG * NP];   // [k][r][n], 4.5 MB

// ---------------- helpers ---------------------------------------------------
__device__ __forceinline__ unsigned long long bcast2(float x) {
    unsigned long long r;
    asm("mov.b64 %0, {%1, %1};" : "=l"(r) : "f"(x));
    return r;
}
__device__ __forceinline__ void ffma2(unsigned long long& d,
                                      unsigned long long a,
                                      unsigned long long b) {
    asm("fma.rn.f32x2 %0, %1, %2, %3;" : "=l"(d) : "l"(a), "l"(b), "l"(d));
}
__device__ __forceinline__ void split2(unsigned& lo, unsigned& hi,
                                       unsigned long long v) {
    asm("mov.b64 {%0, %1}, %2;" : "=r"(lo), "=r"(hi) : "l"(v));
}
__device__ __forceinline__ unsigned prmt(unsigned a, unsigned b, unsigned sel) {
    unsigned d;
    asm("prmt.b32 %0, %1, %2, %3;" : "=r"(d) : "r"(a), "r"(b), "r"(sel));
    return d;
}
__device__ __forceinline__ void cp_async16(void* smem, const void* gmem) {
    unsigned s = (unsigned)__cvta_generic_to_shared(smem);
    asm volatile("cp.async.cg.shared.global [%0], [%1], 16;" :: "r"(s), "l"(gmem));
}
#define CP_COMMIT() asm volatile("cp.async.commit_group;")
#define CP_WAIT0()  asm volatile("cp.async.wait_group 0;")

// ---------------- prep 1: gather x into g_P rows 0..15 (8 n / thread) ------
__global__ void prep1_kernel(const float* __restrict__ x) {
    int idx = blockIdx.x * blockDim.x + threadIdx.x;   // [0, 16*16*512)
    int n8 = idx & 511;
    int rk = idx >> 9;           // k*16 + r
    int k = rk >> 4;
    int r = rk & 15;
    float v[8];
#pragma unroll
    for (int c = 0; c < 8; c++) {
        int n = n8 * 8 + c;
        int h = ((4 * (n & 15) + (r >> 2)) << 4) + (n >> 8);
        int w = ((16 * (r & 3) + k) << 4) + ((n >> 4) & 15);
        v[c] = x[h * 1024 + w];
    }
    float* dst = &g_P[(k * RAUG + r) * NP + n8 * 8];
    *(float4*)dst       = make_float4(v[0], v[1], v[2], v[3]);
    *(float4*)(dst + 4) = make_float4(v[4], v[5], v[6], v[7]);
}

// ---------------- prep 2: augmentation rows 16,17 ---------------------------
__global__ void prep2_kernel() {
    int idx = blockIdx.x * blockDim.x + threadIdx.x;   // [0, 16*1024)
    int n4 = idx & 1023;
    int k = idx >> 10;
    float s[4] = {0.0f, 0.0f, 0.0f, 0.0f};
#pragma unroll
    for (int r = 0; r < 16; r++) {
        float4 v = *(const float4*)&g_P[(k * RAUG + r) * NP + n4 * 4];
        s[0] = fmaf(v.x, v.x, s[0]);
        s[1] = fmaf(v.y, v.y, s[1]);
        s[2] = fmaf(v.z, v.z, s[2]);
        s[3] = fmaf(v.w, v.w, s[3]);
    }
    *(float4*)&g_P[(k * RAUG + 16) * NP + n4 * 4] =
        make_float4(1.0f, 1.0f, 1.0f, 1.0f);
    *(float4*)&g_P[(k * RAUG + 17) * NP + n4 * 4] =
        make_float4(12.25f - 0.5f * s[0], 12.25f - 0.5f * s[1],
                    12.25f - 0.5f * s[2], 12.25f - 0.5f * s[3]);
}

// ---------------- main: tiled pair kernel -----------------------------------
// Tile 64 i x 128 j, 128 threads, 8x8 per thread.
// j frag = {tx*4..+3} U {64+tx*4..+3}  (16B lane stride -> conflict-free LDS).
// Sign-bit OR fold via PRMT: 2 x u32 masks per (ii) pair-group, 16 mask regs.
__global__ void __launch_bounds__(128, 4) gram_kernel(float* __restrict__ A) {
    const int bid = blockIdx.x;
    int jb = (int)(0.5f * (sqrtf(4.0f * (float)bid + 1.0f) - 1.0f));
    while (jb * (jb + 1) > bid) jb--;
    while ((jb + 1) * (jb + 2) <= bid) jb++;
    const int ib = bid - jb * (jb + 1);        // 0 .. 2*jb+1

    __shared__ __align__(16) float sA[2][RAUG][64];
    __shared__ __align__(16) float sB[2][RAUG][128];

    const int tid = threadIdx.x;
    const int tx = tid & 15;             // j group
    const int ty = tid >> 4;             // i group 0..7
    const int i0 = ib * 64;
    const int j0 = jb * 128;

    auto issue = [&](int buf, int k) {
#pragma unroll
        for (int idx = tid; idx < 288; idx += 128) {     // sA: 18 x 16 float4
            int r = idx >> 4, c = idx & 15;
            cp_async16(&sA[buf][r][c * 4], &g_P[(k * RAUG + r) * NP + i0 + c * 4]);
        }
#pragma unroll
        for (int idx = tid; idx < 576; idx += 128) {     // sB: 18 x 32 float4
            int r = idx >> 5, c = idx & 31;
            int rs = (r < 16) ? r : (33 - r);            // rows 16/17 swapped
            cp_async16(&sB[buf][r][c * 4], &g_P[(k * RAUG + rs) * NP + j0 + c * 4]);
        }
    };

    unsigned msk[8][2];
#pragma unroll
    for (int a = 0; a < 8; a++) { msk[a][0] = 0u; msk[a][1] = 0u; }

    issue(0, 0);
    CP_COMMIT();

#pragma unroll 1
    for (int k = 0; k < 16; k++) {
        const int buf = k & 1;
        CP_WAIT0();
        __syncthreads();          // buf staged AND everyone done with buf^1
        if (k < 15) {
            issue(buf ^ 1, k + 1);
            CP_COMMIT();
        }

        unsigned long long acc[8][4];
#pragma unroll
        for (int a = 0; a < 8; a++)
#pragma unroll
            for (int b = 0; b < 4; b++) acc[a][b] = 0ULL;

#pragma unroll
        for (int r = 0; r < RAUG; r++) {
            float4 a0 = *(const float4*)&sA[buf][r][ty * 8];
            float4 a1 = *(const float4*)&sA[buf][r][ty * 8 + 4];
            ulonglong2 b0 = *(const ulonglong2*)&sB[buf][r][tx * 4];
            ulonglong2 b1 = *(const ulonglong2*)&sB[buf][r][64 + tx * 4];
            unsigned long long bb[4] = {b0.x, b0.y, b1.x, b1.y};
            float av[8] = {a0.x, a0.y, a0.z, a0.w, a1.x, a1.y, a1.z, a1.w};
#pragma unroll
            for (int ii = 0; ii < 8; ii++) {
                unsigned long long aa = bcast2(av[ii]);
#pragma unroll
                for (int jj = 0; jj < 4; jj++) ffma2(acc[ii][jj], aa, bb[jj]);
            }
        }

        // fold sign bits: msk[ii][p] bytes = signs of j elements (p*64+tx*4+0..3)
#pragma unroll
        for (int ii = 0; ii < 8; ii++)
#pragma unroll
            for (int p = 0; p < 2; p++) {
                unsigned lo0, hi0, lo1, hi1;
                split2(lo0, hi0, acc[ii][2 * p]);
                split2(lo1, hi1, acc[ii][2 * p + 1]);
                unsigned t0 = prmt(lo0, hi0, 0xFBFBu);  // [s_lo0,s_hi0,...]
                unsigned t1 = prmt(lo1, hi1, 0xFBFBu);
                unsigned u  = prmt(t0, t1, 0x5410u);    // [s0,s1,s2,s3]
                msk[ii][p] |= u;
            }
        // NOTE: no trailing sync needed; next iteration's CP_WAIT0+sync covers it
    }

    // ---- epilogue: byte==0 -> 1.0f ----
    // direct: A[i, j]
#pragma unroll
    for (int ii = 0; ii < 8; ii++)
#pragma unroll
        for (int p = 0; p < 2; p++) {
            unsigned m = msk[ii][p];
            float4 o;
            o.x = (m & 0x00000080u) ? 0.0f : 1.0f;
            o.y = (m & 0x00008000u) ? 0.0f : 1.0f;
            o.z = (m & 0x00800000u) ? 0.0f : 1.0f;
            o.w = (m & 0x80000000u) ? 0.0f : 1.0f;
            size_t off = (size_t)(i0 + ty * 8 + ii) * 4096 + j0 + p * 64 + tx * 4;
            *(float4*)&A[off] = o;
        }
    // transposed: A[j, i]; skip rows already covered by direct writes (diag tiles)
#pragma unroll
    for (int p = 0; p < 2; p++)
#pragma unroll
        for (int c = 0; c < 4; c++) {
            int rowj = j0 + p * 64 + tx * 4 + c;
            if (rowj >= i0 && rowj < i0 + 64) continue;   // handled by direct side
            unsigned bit = 0x80u << (8 * c);
            float4 o0, o1;
            o0.x = (msk[0][p] & bit) ? 0.0f : 1.0f;
            o0.y = (msk[1][p] & bit) ? 0.0f : 1.0f;
            o0.z = (msk[2][p] & bit) ? 0.0f : 1.0f;
            o0.w = (msk[3][p] & bit) ? 0.0f : 1.0f;
            o1.x = (msk[4][p] & bit) ? 0.0f : 1.0f;
            o1.y = (msk[5][p] & bit) ? 0.0f : 1.0f;
            o1.z = (msk[6][p] & bit) ? 0.0f : 1.0f;
            o1.w = (msk[7][p] & bit) ? 0.0f : 1.0f;
            size_t off = (size_t)rowj * 4096 + i0 + ty * 8;
            *(float4*)&A[off]     = o0;
            *(float4*)&A[off + 4] = o1;
        }
}

// ---------------------------------------------------------------------------
extern "C" void kernel_launch(void* const* d_in, const int* in_sizes, int n_in,
                              void* d_out, int out_size) {
    const float* x = (const float*)d_in[0];
    float* A = (float*)d_out;

    prep1_kernel<<<512, 256>>>(x);         // 16*16*512 threads, 8 n each
    prep2_kernel<<<64, 256>>>();           // 16*1024 threads, 4 n each
    gram_kernel<<<1056, 128>>>(A);         // exact triangle of 64x128 tiles
}